// round 2
// baseline (speedup 1.0000x reference)
#include <cuda_runtime.h>
#include <cuda_fp16.h>
#include <math.h>

#define HASHMAP_SIZE 32768
#define HASH_MASK 32767u
#define L0_ENTRIES 4913   /* 17^3, res 16 dense */
#define L1_ENTRIES 15625  /* 25^3, res 24 dense */
#define SMEM_L0_BYTES (L0_ENTRIES * 16)
#define SMEM_L1_BYTES (L1_ENTRIES * 8)
#define SMEM_TOTAL (SMEM_L0_BYTES + SMEM_L1_BYTES)
#define SC_UP   16384.0f
#define SC_DOWN (1.0f / 16384.0f)

// MLP weights in constant memory -> uniform-const port (LDCU), off the l1tex pipe
__constant__ float cW1[16 * 32];
__constant__ float cb1[32];
__constant__ float cW2[32 * 16];
__constant__ float cb2[16];
__constant__ float cW3[16 * 8];
__constant__ float cb3[8];
__constant__ float cW4[8 * 3];
__constant__ float cb4[3];

__global__ void __launch_bounds__(768, 1)
hashmlp_kernel(const float* __restrict__ dirs,
               const float* __restrict__ grid,
               float* __restrict__ out, int n)
{
    extern __shared__ char smem_raw[];
    float4* sL0 = (float4*)smem_raw;                       // level 0, fp32
    uint2*  sL1 = (uint2*)(smem_raw + SMEM_L0_BYTES);      // level 1, fp16x4 scaled

    const int tid = threadIdx.x;
    const int bs  = blockDim.x;

    // ---- stage dense levels into smem ----
    {
        const float4* g0 = (const float4*)grid;                    // level 0 base
        for (int i = tid; i < L0_ENTRIES; i += bs)
            sL0[i] = __ldg(g0 + i);
        const float4* g1 = (const float4*)grid + HASHMAP_SIZE;     // level 1 base
        for (int i = tid; i < L1_ENTRIES; i += bs) {
            float4 v = __ldg(g1 + i);
            __half2 h01 = __floats2half2_rn(v.x * SC_UP, v.y * SC_UP);
            __half2 h23 = __floats2half2_rn(v.z * SC_UP, v.w * SC_UP);
            uint2 u;
            u.x = *reinterpret_cast<unsigned*>(&h01);
            u.y = *reinterpret_cast<unsigned*>(&h23);
            sL1[i] = u;
        }
    }
    __syncthreads();

    const int stride = gridDim.x * blockDim.x;
    for (int gid = blockIdx.x * blockDim.x + tid; gid < n; gid += stride) {

        float dx = dirs[gid * 3 + 0];
        float dy = dirs[gid * 3 + 1];
        float dz = dirs[gid * 3 + 2];

        float feats[16];

        // ---------- level 0: res 16, dense, fp32 in smem ----------
        {
            const int res = 16;
            float px = dx * (float)res, py = dy * (float)res, pz = dz * (float)res;
            float fx0 = floorf(px), fy0 = floorf(py), fz0 = floorf(pz);
            float fx = px - fx0, fy = py - fy0, fz = pz - fz0;
            int ix0 = (int)fx0, iy0 = (int)fy0, iz0 = (int)fz0;
            float wx[2] = {1.0f - fx, fx}, wy[2] = {1.0f - fy, fy}, wz[2] = {1.0f - fz, fz};
            float a0 = 0.f, a1 = 0.f, a2 = 0.f, a3 = 0.f;
            #pragma unroll
            for (int c = 0; c < 8; c++) {
                int bx = (c >> 2) & 1, by = (c >> 1) & 1, bz = c & 1;
                int cx = min(max(ix0 + bx, 0), res);
                int cy = min(max(iy0 + by, 0), res);
                int cz = min(max(iz0 + bz, 0), res);
                int idx = cx + 17 * (cy + 17 * cz);
                float w = wx[bx] * wy[by] * wz[bz];
                float4 v = sL0[idx];
                a0 = fmaf(w, v.x, a0); a1 = fmaf(w, v.y, a1);
                a2 = fmaf(w, v.z, a2); a3 = fmaf(w, v.w, a3);
            }
            feats[0] = a0; feats[1] = a1; feats[2] = a2; feats[3] = a3;
        }

        // ---------- level 1: res 24, dense, fp16 (scaled) in smem ----------
        {
            const int res = 24;
            float px = dx * (float)res, py = dy * (float)res, pz = dz * (float)res;
            float fx0 = floorf(px), fy0 = floorf(py), fz0 = floorf(pz);
            float fx = px - fx0, fy = py - fy0, fz = pz - fz0;
            int ix0 = (int)fx0, iy0 = (int)fy0, iz0 = (int)fz0;
            float wx[2] = {1.0f - fx, fx}, wy[2] = {1.0f - fy, fy}, wz[2] = {1.0f - fz, fz};
            float a0 = 0.f, a1 = 0.f, a2 = 0.f, a3 = 0.f;
            #pragma unroll
            for (int c = 0; c < 8; c++) {
                int bx = (c >> 2) & 1, by = (c >> 1) & 1, bz = c & 1;
                int cx = min(max(ix0 + bx, 0), res);
                int cy = min(max(iy0 + by, 0), res);
                int cz = min(max(iz0 + bz, 0), res);
                int idx = cx + 25 * (cy + 25 * cz);
                float w = wx[bx] * wy[by] * wz[bz] * SC_DOWN;
                uint2 u = sL1[idx];
                __half2 h01 = *reinterpret_cast<__half2*>(&u.x);
                __half2 h23 = *reinterpret_cast<__half2*>(&u.y);
                float2 f01 = __half22float2(h01);
                float2 f23 = __half22float2(h23);
                a0 = fmaf(w, f01.x, a0); a1 = fmaf(w, f01.y, a1);
                a2 = fmaf(w, f23.x, a2); a3 = fmaf(w, f23.y, a3);
            }
            feats[4] = a0; feats[5] = a1; feats[6] = a2; feats[7] = a3;
        }

        // ---------- levels 2,3: hashed, fp32 LDG ----------
        #pragma unroll
        for (int l = 2; l < 4; l++) {
            const int res = (l == 2) ? 36 : 54;
            float px = dx * (float)res, py = dy * (float)res, pz = dz * (float)res;
            float fx0 = floorf(px), fy0 = floorf(py), fz0 = floorf(pz);
            float fx = px - fx0, fy = py - fy0, fz = pz - fz0;
            int ix0 = (int)fx0, iy0 = (int)fy0, iz0 = (int)fz0;
            float wx[2] = {1.0f - fx, fx}, wy[2] = {1.0f - fy, fy}, wz[2] = {1.0f - fz, fz};
            float a0 = 0.f, a1 = 0.f, a2 = 0.f, a3 = 0.f;
            const float4* gl = (const float4*)grid + (size_t)l * HASHMAP_SIZE;
            #pragma unroll
            for (int c = 0; c < 8; c++) {
                int bx = (c >> 2) & 1, by = (c >> 1) & 1, bz = c & 1;
                int cx = min(max(ix0 + bx, 0), res);
                int cy = min(max(iy0 + by, 0), res);
                int cz = min(max(iz0 + bz, 0), res);
                unsigned int h = (unsigned int)cx
                               ^ ((unsigned int)cy * 2654435761u)
                               ^ ((unsigned int)cz * 805459861u);
                int idx = (int)(h & HASH_MASK);
                float w = wx[bx] * wy[by] * wz[bz];
                float4 v = __ldg(gl + idx);
                a0 = fmaf(w, v.x, a0); a1 = fmaf(w, v.y, a1);
                a2 = fmaf(w, v.z, a2); a3 = fmaf(w, v.w, a3);
            }
            feats[l * 4 + 0] = a0; feats[l * 4 + 1] = a1;
            feats[l * 4 + 2] = a2; feats[l * 4 + 3] = a3;
        }

        // ---------- MLP: 16 -> 32 -> 16 -> 8 -> 3 (weights via const port) ----------
        float h1[32];
        #pragma unroll
        for (int j = 0; j < 32; j++) {
            float acc = cb1[j];
            #pragma unroll
            for (int i = 0; i < 16; i++) acc = fmaf(feats[i], cW1[i * 32 + j], acc);
            h1[j] = (acc > 0.f) ? acc : 0.2f * acc;
        }

        float h2[16];
        #pragma unroll
        for (int j = 0; j < 16; j++) {
            float acc = cb2[j];
            #pragma unroll
            for (int i = 0; i < 32; i++) acc = fmaf(h1[i], cW2[i * 16 + j], acc);
            h2[j] = (acc > 0.f) ? acc : 0.2f * acc;
        }

        float h3[8];
        #pragma unroll
        for (int j = 0; j < 8; j++) {
            float acc = cb3[j];
            #pragma unroll
            for (int i = 0; i < 16; i++) acc = fmaf(h2[i], cW3[i * 8 + j], acc);
            h3[j] = (acc > 0.f) ? acc : 0.2f * acc;
        }

        #pragma unroll
        for (int j = 0; j < 3; j++) {
            float acc = cb4[j];
            #pragma unroll
            for (int i = 0; i < 8; i++) acc = fmaf(h3[i], cW4[i * 3 + j], acc);
            out[gid * 3 + j] = tanhf(acc);
        }
    }
}

extern "C" void kernel_launch(void* const* d_in, const int* in_sizes, int n_in,
                              void* d_out, int out_size) {
    const float* dirs = (const float*)d_in[0];
    const float* grid = (const float*)d_in[1];
    float* out = (float*)d_out;
    int n = in_sizes[0] / 3;

    // weights -> constant memory (device-to-device, graph-capturable)
    cudaMemcpyToSymbolAsync(cW1, d_in[2], 16 * 32 * sizeof(float), 0, cudaMemcpyDeviceToDevice);
    cudaMemcpyToSymbolAsync(cb1, d_in[3], 32 * sizeof(float),      0, cudaMemcpyDeviceToDevice);
    cudaMemcpyToSymbolAsync(cW2, d_in[4], 32 * 16 * sizeof(float), 0, cudaMemcpyDeviceToDevice);
    cudaMemcpyToSymbolAsync(cb2, d_in[5], 16 * sizeof(float),      0, cudaMemcpyDeviceToDevice);
    cudaMemcpyToSymbolAsync(cW3, d_in[6], 16 * 8 * sizeof(float),  0, cudaMemcpyDeviceToDevice);
    cudaMemcpyToSymbolAsync(cb3, d_in[7], 8 * sizeof(float),       0, cudaMemcpyDeviceToDevice);
    cudaMemcpyToSymbolAsync(cW4, d_in[8], 8 * 3 * sizeof(float),   0, cudaMemcpyDeviceToDevice);
    cudaMemcpyToSymbolAsync(cb4, d_in[9], 3 * sizeof(float),       0, cudaMemcpyDeviceToDevice);

    cudaFuncSetAttribute(hashmlp_kernel, cudaFuncAttributeMaxDynamicSharedMemorySize, SMEM_TOTAL);

    int dev = 0, sms = 148;
    cudaGetDevice(&dev);
    cudaDeviceGetAttribute(&sms, cudaDevAttrMultiProcessorCount, dev);

    int threads = 768;
    int blocks = 2 * sms;   // 1 resident block/SM (203.6 KB smem), 2 sequential fills
    hashmlp_kernel<<<blocks, threads, SMEM_TOTAL>>>(dirs, grid, out, n);
}

// round 16
// speedup vs baseline: 1.6663x; 1.6663x over previous
#include <cuda_runtime.h>
#include <math.h>

#define HASHMAP_SIZE 32768
#define HASH_MASK 32767u
#define P1 2654435761u
#define P2 805459861u

// MLP weights in constant memory (uniform-const LDCU port)
__constant__ float cW1[16 * 32];
__constant__ float cb1[32];
__constant__ float cW2[32 * 16];
__constant__ float cb2[16];
__constant__ float cW3[16 * 8];
__constant__ float cb3[8];
__constant__ float cW4[8 * 3];
__constant__ float cb4[3];

typedef unsigned long long u64;

__device__ __forceinline__ u64 pk2(float a, float b) {
    u64 r;
    asm("mov.b64 %0, {%1, %2};" : "=l"(r)
        : "r"(__float_as_uint(a)), "r"(__float_as_uint(b)));
    return r;
}
__device__ __forceinline__ void upk2(u64 v, float& a, float& b) {
    unsigned x, y;
    asm("mov.b64 {%0, %1}, %2;" : "=r"(x), "=r"(y) : "l"(v));
    a = __uint_as_float(x);
    b = __uint_as_float(y);
}
__device__ __forceinline__ u64 fma2(u64 a, u64 b, u64 c) {
    u64 d;
    asm("fma.rn.f32x2 %0, %1, %2, %3;" : "=l"(d) : "l"(a), "l"(b), "l"(c));
    return d;
}
// accurate fast tanh: (1-e)/(1+e) with e = exp(-2|x|); rel err ~1e-6
__device__ __forceinline__ float tanh_acc(float x) {
    float ax = fabsf(x);
    float e;
    asm("ex2.approx.f32 %0, %1;" : "=f"(e) : "f"(ax * -2.885390082f)); // -2*log2(e)
    float r = __fdividef(1.f - e, 1.f + e);
    return copysignf(r, x);
}
__device__ __forceinline__ float leaky(float x) {
    return (x > 0.f) ? x : 0.2f * x;
}

__global__ void __launch_bounds__(256, 4)
hashmlp_kernel(const float* __restrict__ dirs,
               const float* __restrict__ grid,
               float* __restrict__ out, int n)
{
    int gid = blockIdx.x * blockDim.x + threadIdx.x;
    if (gid >= n) return;

    float dx = dirs[gid * 3 + 0];
    float dy = dirs[gid * 3 + 1];
    float dz = dirs[gid * 3 + 2];

    const u64* W1p = (const u64*)cW1;  const u64* b1p = (const u64*)cb1;
    const u64* W2p = (const u64*)cW2;  const u64* b2p = (const u64*)cb2;
    const u64* W3p = (const u64*)cW3;  const u64* b3p = (const u64*)cb3;

    // Layer-1 accumulators (32 outputs = 16 f32x2 pairs), seeded with bias.
    // Hashgrid features are folded in level-by-level so feats[] never lives.
    u64 acc1[16];
    #pragma unroll
    for (int p = 0; p < 16; p++) acc1[p] = b1p[p];

    #pragma unroll
    for (int l = 0; l < 4; l++) {
        const int res = (l == 0) ? 16 : (l == 1) ? 24 : (l == 2) ? 36 : 54;
        float px = dx * (float)res, py = dy * (float)res, pz = dz * (float)res;
        float fx0 = floorf(px), fy0 = floorf(py), fz0 = floorf(pz);
        float fx = px - fx0, fy = py - fy0, fz = pz - fz0;
        int ix0 = (int)fx0, iy0 = (int)fy0, iz0 = (int)fz0;
        float wx0 = 1.f - fx, wx1 = fx;
        float wy0 = 1.f - fy, wy1 = fy;
        float wz0 = 1.f - fz, wz1 = fz;
        float w00 = wy0 * wz0, w10 = wy1 * wz0, w01 = wy0 * wz1, w11 = wy1 * wz1;

        const float4* gl = (const float4*)grid + (size_t)l * HASHMAP_SIZE;
        float a0 = 0.f, a1 = 0.f, a2 = 0.f, a3 = 0.f;

        if (l < 2) {
            // dense level; dirs in [0,1) => no clamp needed, indices in-bounds
            const int s = res + 1, s2 = s * s;
            int base = ix0 + s * iy0 + s2 * iz0;
            #pragma unroll
            for (int c = 0; c < 8; c++) {
                int bx = c & 1, by = (c >> 1) & 1, bz = (c >> 2) & 1;
                int idx = base + bx + (by ? s : 0) + (bz ? s2 : 0);
                float wyz = by ? (bz ? w11 : w10) : (bz ? w01 : w00);
                float w = (bx ? wx1 : wx0) * wyz;
                float4 v = __ldg(gl + idx);
                a0 = fmaf(w, v.x, a0); a1 = fmaf(w, v.y, a1);
                a2 = fmaf(w, v.z, a2); a3 = fmaf(w, v.w, a3);
            }
        } else {
            // hashed level; per-axis hash terms hoisted
            unsigned hx0 = (unsigned)ix0, hx1 = hx0 + 1u;
            unsigned hy0 = (unsigned)iy0 * P1, hy1 = hy0 + P1;
            unsigned hz0 = (unsigned)iz0 * P2, hz1 = hz0 + P2;
            #pragma unroll
            for (int c = 0; c < 8; c++) {
                int bx = c & 1, by = (c >> 1) & 1, bz = (c >> 2) & 1;
                unsigned h = (bx ? hx1 : hx0) ^ (by ? hy1 : hy0) ^ (bz ? hz1 : hz0);
                int idx = (int)(h & HASH_MASK);
                float wyz = by ? (bz ? w11 : w10) : (bz ? w01 : w00);
                float w = (bx ? wx1 : wx0) * wyz;
                float4 v = __ldg(gl + idx);
                a0 = fmaf(w, v.x, a0); a1 = fmaf(w, v.y, a1);
                a2 = fmaf(w, v.z, a2); a3 = fmaf(w, v.w, a3);
            }
        }

        // fold this level's 4 features into layer-1 accumulators (rows l*4..l*4+3)
        float fv[4] = {a0, a1, a2, a3};
        #pragma unroll
        for (int k = 0; k < 4; k++) {
            u64 xi = pk2(fv[k], fv[k]);
            #pragma unroll
            for (int p = 0; p < 16; p++)
                acc1[p] = fma2(xi, W1p[(l * 4 + k) * 16 + p], acc1[p]);
        }
    }

    // leaky on layer-1 outputs
    float h1[32];
    #pragma unroll
    for (int p = 0; p < 16; p++) {
        float a, b; upk2(acc1[p], a, b);
        h1[2 * p] = leaky(a); h1[2 * p + 1] = leaky(b);
    }

    // L2: 32 -> 16 (8 pairs)
    u64 acc2[8];
    #pragma unroll
    for (int p = 0; p < 8; p++) acc2[p] = b2p[p];
    #pragma unroll
    for (int i = 0; i < 32; i++) {
        u64 xi = pk2(h1[i], h1[i]);
        #pragma unroll
        for (int p = 0; p < 8; p++) acc2[p] = fma2(xi, W2p[i * 8 + p], acc2[p]);
    }
    float h2[16];
    #pragma unroll
    for (int p = 0; p < 8; p++) {
        float a, b; upk2(acc2[p], a, b);
        h2[2 * p] = leaky(a); h2[2 * p + 1] = leaky(b);
    }

    // L3: 16 -> 8 (4 pairs)
    u64 acc3[4];
    #pragma unroll
    for (int p = 0; p < 4; p++) acc3[p] = b3p[p];
    #pragma unroll
    for (int i = 0; i < 16; i++) {
        u64 xi = pk2(h2[i], h2[i]);
        #pragma unroll
        for (int p = 0; p < 4; p++) acc3[p] = fma2(xi, W3p[i * 4 + p], acc3[p]);
    }
    float h3[8];
    #pragma unroll
    for (int p = 0; p < 4; p++) {
        float a, b; upk2(acc3[p], a, b);
        h3[2 * p] = leaky(a); h3[2 * p + 1] = leaky(b);
    }

    // L4: 8 -> 3 (scalar), accurate fast tanh
    #pragma unroll
    for (int j = 0; j < 3; j++) {
        float acc = cb4[j];
        #pragma unroll
        for (int i = 0; i < 8; i++) acc = fmaf(h3[i], cW4[i * 3 + j], acc);
        out[gid * 3 + j] = tanh_acc(acc);
    }
}

extern "C" void kernel_launch(void* const* d_in, const int* in_sizes, int n_in,
                              void* d_out, int out_size) {
    const float* dirs = (const float*)d_in[0];
    const float* grid = (const float*)d_in[1];
    float* out = (float*)d_out;
    int n = in_sizes[0] / 3;

    cudaMemcpyToSymbolAsync(cW1, d_in[2], 16 * 32 * sizeof(float), 0, cudaMemcpyDeviceToDevice);
    cudaMemcpyToSymbolAsync(cb1, d_in[3], 32 * sizeof(float),      0, cudaMemcpyDeviceToDevice);
    cudaMemcpyToSymbolAsync(cW2, d_in[4], 32 * 16 * sizeof(float), 0, cudaMemcpyDeviceToDevice);
    cudaMemcpyToSymbolAsync(cb2, d_in[5], 16 * sizeof(float),      0, cudaMemcpyDeviceToDevice);
    cudaMemcpyToSymbolAsync(cW3, d_in[6], 16 * 8 * sizeof(float),  0, cudaMemcpyDeviceToDevice);
    cudaMemcpyToSymbolAsync(cb3, d_in[7], 8 * sizeof(float),       0, cudaMemcpyDeviceToDevice);
    cudaMemcpyToSymbolAsync(cW4, d_in[8], 8 * 3 * sizeof(float),   0, cudaMemcpyDeviceToDevice);
    cudaMemcpyToSymbolAsync(cb4, d_in[9], 3 * sizeof(float),       0, cudaMemcpyDeviceToDevice);

    int threads = 256;
    int blocks = (n + threads - 1) / threads;
    hashmlp_kernel<<<blocks, threads>>>(dirs, grid, out, n);
}